// round 4
// baseline (speedup 1.0000x reference)
#include <cuda_runtime.h>
#include <cuda_bf16.h>

#define DIM 128
#define TEMP_INV (1.0f / 0.07f)

// Flag set by the detection kernel: 1 if index buffers are int64, 0 if int32.
__device__ int g_idx_is64;

// Index values are uniform in [0, 1e6) -> fit in 20 bits. If little-endian
// int64, every odd 32-bit word is zero. If int32, odd words are random;
// P(64 all zero) ~ 0.
__global__ void detect_idx_kernel(const unsigned int* __restrict__ idx_words) {
    if (threadIdx.x == 0) {
        unsigned int acc = 0;
#pragma unroll
        for (int i = 1; i < 128; i += 2) acc |= idx_words[i];
        g_idx_is64 = (acc == 0) ? 1 : 0;
    }
}

__device__ __forceinline__ float dot4(float4 a, float4 b) {
    return a.x * b.x + a.y * b.y + a.z * b.z + a.w * b.w;
}

__global__ __launch_bounds__(256, 6)
void la_loss_kernel(const float* __restrict__ codes,
                    const float* __restrict__ bank,
                    const void* __restrict__ idx_bg,
                    const void* __restrict__ idx_cl,
                    float* __restrict__ out,
                    int K)
{
    const int b    = blockIdx.x;
    const int tid  = threadIdx.x;
    const int wid  = tid >> 5;      // 0..7
    const int lane = tid & 31;
    const int grp  = lane >> 4;     // 0 or 1: half-warp row group
    const int gl   = lane & 15;     // lane within group
    const bool is64 = (g_idx_is64 != 0);

    const float4* __restrict__ bank4  = reinterpret_cast<const float4*>(bank);
    const float4* __restrict__ codes4 = reinterpret_cast<const float4*>(codes);

    // ---- v: each lane holds float4 #gl and #(16+gl) of the 128-dim code row.
    // Each 16-lane group holds the FULL vector -> 4-step butterfly suffices.
    float4 va = codes4[(size_t)b * 32 + gl];
    float4 vb = codes4[(size_t)b * 32 + 16 + gl];
    float ss = dot4(va, va) + dot4(vb, vb);
#pragma unroll
    for (int o = 8; o; o >>= 1) ss += __shfl_xor_sync(0xffffffffu, ss, o);
    const float rn = rsqrtf(ss);
    va.x *= rn; va.y *= rn; va.z *= rn; va.w *= rn;
    vb.x *= rn; vb.y *= rn; vb.z *= rn; vb.w *= rn;

    // warps 0-3 -> background, 4-7 -> close. Row for iteration t:
    //   m = t*8 + wsub*2 + grp   (4 warps x 2 groups = 8 rows per t-step)
    const void* idx = (wid < 4) ? idx_bg : idx_cl;
    const int wsub = wid & 3;
    const size_t base = (size_t)b * (size_t)K;
    const int moff = wsub * 2 + grp;
    const int iters = (K + 7) >> 3;   // all lanes run the same count

    // ---- software pipeline: prefetch iteration 0 ----
    int m = moff;
    long long ii;
    {
        int mc = (m < K) ? m : 0;
        if (is64) ii = reinterpret_cast<const long long*>(idx)[base + mc];
        else      ii = (long long)reinterpret_cast<const int*>(idx)[base + mc];
    }
    float4 r0 = bank4[(size_t)ii * 32 + gl];
    float4 r1 = bank4[(size_t)ii * 32 + 16 + gl];

    float acc = 0.0f;
    for (int t = 0; t < iters; t++) {
        const int mcur = m;
        float4 c0 = r0, c1 = r1;

        // prefetch next iteration's row while reducing this one
        m += 8;
        if (t + 1 < iters) {
            int mc = (m < K) ? m : 0;
            if (is64) ii = reinterpret_cast<const long long*>(idx)[base + mc];
            else      ii = (long long)reinterpret_cast<const int*>(idx)[base + mc];
            r0 = bank4[(size_t)ii * 32 + gl];
            r1 = bank4[(size_t)ii * 32 + 16 + gl];
        }

        float d = dot4(c0, va) + dot4(c1, vb);
#pragma unroll
        for (int o = 8; o; o >>= 1) d += __shfl_xor_sync(0xffffffffu, d, o);
        if (mcur < K) acc += __expf(d * TEMP_INV);
    }

    // combine the two half-warp groups
    acc += __shfl_xor_sync(0xffffffffu, acc, 16);

    __shared__ float s[8];
    if (lane == 0) s[wid] = acc;
    __syncthreads();
    if (tid == 0) {
        float d1 = s[0] + s[1] + s[2] + s[3];
        float d2 = s[4] + s[5] + s[6] + s[7];
        out[b] = logf(d1) - logf(d2);
    }
}

extern "C" void kernel_launch(void* const* d_in, const int* in_sizes, int n_in,
                              void* d_out, int out_size) {
    const float* codes = (const float*)d_in[0];
    const float* bank  = (const float*)d_in[1];
    const void*  ibg   = d_in[2];
    const void*  icl   = d_in[3];
    float* out = (float*)d_out;

    const int B = out_size;                 // 1024
    const int K = in_sizes[2] / B;          // 200

    detect_idx_kernel<<<1, 32>>>((const unsigned int*)ibg);
    la_loss_kernel<<<B, 256>>>(codes, bank, ibg, icl, out, K);
}

// round 5
// speedup vs baseline: 1.0982x; 1.0982x over previous
#include <cuda_runtime.h>
#include <cuda_bf16.h>

#define DIM 128
#define TEMP_INV (1.0f / 0.07f)
#define STAGES 6

// Flag set by the detection kernel: 1 if index buffers are int64, 0 if int32.
__device__ int g_idx_is64;

// Index values are uniform in [0, 1e6) -> fit in 20 bits. If little-endian
// int64, every odd 32-bit word is zero. If int32, odd words are random;
// P(64 all zero) ~ 0.
__global__ void detect_idx_kernel(const unsigned int* __restrict__ idx_words) {
    if (threadIdx.x == 0) {
        unsigned int acc = 0;
#pragma unroll
        for (int i = 1; i < 128; i += 2) acc |= idx_words[i];
        g_idx_is64 = (acc == 0) ? 1 : 0;
    }
}

__device__ __forceinline__ float dot4(float4 a, float4 b) {
    return a.x * b.x + a.y * b.y + a.z * b.z + a.w * b.w;
}

__global__ __launch_bounds__(256, 8)
void la_loss_kernel(const float* __restrict__ codes,
                    const float* __restrict__ bank,
                    const void* __restrict__ idx_bg,
                    const void* __restrict__ idx_cl,
                    float* __restrict__ out,
                    int K)
{
    // per-warp private ring buffers: 8 warps x 6 stages x 512B = 24KB
    __shared__ float4 buf[8][STAGES][32];
    __shared__ float s[8];

    const int b    = blockIdx.x;
    const int tid  = threadIdx.x;
    const int wid  = tid >> 5;      // 0..7
    const int lane = tid & 31;
    const bool is64 = (g_idx_is64 != 0);

    // ---- load this batch row's code vector and normalize (per-warp) ----
    float4 c4 = reinterpret_cast<const float4*>(codes + (size_t)b * DIM)[lane];
    float ss = dot4(c4, c4);
#pragma unroll
    for (int o = 16; o; o >>= 1) ss += __shfl_xor_sync(0xffffffffu, ss, o);
    const float rn = rsqrtf(ss);
    const float4 v4 = make_float4(c4.x * rn, c4.y * rn, c4.z * rn, c4.w * rn);

    // warps 0-3 -> background indices, warps 4-7 -> close indices
    const void* idx = (wid < 4) ? idx_bg : idx_cl;
    const int wsub = wid & 3;
    const size_t base = (size_t)b * (size_t)K;
    const int iters = (K - wsub + 3) >> 2;   // rows this warp owns

    // ---- fill helper: row f of this warp into ring slot, or empty group ----
    // (an empty commit_group completes immediately; keeps group count uniform)
    auto fill = [&](int f, int slot) {
        if (f < iters) {
            int m = wsub + 4 * f;
            long long ii;
            if (is64) ii = reinterpret_cast<const long long*>(idx)[base + m];
            else      ii = (long long)reinterpret_cast<const int*>(idx)[base + m];
            const float4* src = reinterpret_cast<const float4*>(bank + (size_t)ii * DIM) + lane;
            unsigned sad = (unsigned)__cvta_generic_to_shared(&buf[wid][slot][lane]);
            asm volatile("cp.async.cg.shared.global [%0], [%1], 16;\n"
                         :: "r"(sad), "l"(src));
        }
        asm volatile("cp.async.commit_group;\n");
    };

    // prologue: fill 6 stages (groups 0..5 pending)
#pragma unroll
    for (int f = 0; f < STAGES; f++) fill(f, f);

    float acc = 0.0f;
    int slot = 0;
    for (int t = 0; t < iters; t++) {
        // oldest of the 6 pending groups (this iteration's row) is complete
        asm volatile("cp.async.wait_group %0;\n" :: "n"(STAGES - 1));
        float4 r = buf[wid][slot][lane];   // each lane reads the 16B it filled

        // refill this slot with row t+6 (or empty group past the end)
        fill(t + STAGES, slot);
        if (++slot == STAGES) slot = 0;

        float d = dot4(r, v4);
#pragma unroll
        for (int o = 16; o; o >>= 1) d += __shfl_xor_sync(0xffffffffu, d, o);
        acc += __expf(d * TEMP_INV);
    }
    asm volatile("cp.async.wait_group 0;\n");   // drain before exit

    if (lane == 0) s[wid] = acc;
    __syncthreads();
    if (tid == 0) {
        float d1 = s[0] + s[1] + s[2] + s[3];
        float d2 = s[4] + s[5] + s[6] + s[7];
        out[b] = logf(d1) - logf(d2);
    }
}

extern "C" void kernel_launch(void* const* d_in, const int* in_sizes, int n_in,
                              void* d_out, int out_size) {
    const float* codes = (const float*)d_in[0];
    const float* bank  = (const float*)d_in[1];
    const void*  ibg   = d_in[2];
    const void*  icl   = d_in[3];
    float* out = (float*)d_out;

    const int B = out_size;                 // 1024
    const int K = in_sizes[2] / B;          // 200

    detect_idx_kernel<<<1, 32>>>((const unsigned int*)ibg);
    la_loss_kernel<<<B, 256>>>(codes, bank, ibg, icl, out, K);
}